// round 7
// baseline (speedup 1.0000x reference)
#include <cuda_runtime.h>
#include <math.h>

#define NGR    256
#define NPG_   256
#define FDIM   128
#define EPG    4096
#define DLAT   97
#define KTOP   30
#define C1_    16
#define C2_    32
#define T2_    11
#define DENSE_ 352
#define NT     256

typedef unsigned int u32;

// shared layout (float units)
#define OFF_H1    0        // 8192
#define OFF_H2    8192     // 8192
#define OFF_H3    16384    // 8192
#define OFF_G     24576    // 8224 (257 rows x 32, row 256 = zeros)
#define OFF_Z4    32800    // 256
#define OFF_INVD  33056    // 256
#define OFF_WS0   33312    // 4224 (transposed pitch-132)
#define OFF_WS1   37536    // 1024
#define OFF_WS2   38560    // 1024
#define OFF_BS    39584    // 96
#define OFF_SCR   39680    // 8192 (two 4096 cp.async buffers; later reused as scratch)
#define OFF_OFFS  47872    // 257 ints
#define OFF_CNT   48129    // 256 ints
#define OFF_ELIST 48388    // 6144 ints (16B aligned)
#define SM_FLOATS (48388 + 6144)
static const int SMEM_BYTES = SM_FLOATS * 4;   // ~218KB

__device__ __forceinline__ void cp16(u32 saddr, const void* gaddr) {
    asm volatile("cp.async.cg.shared.global [%0], [%1], 16;" :: "r"(saddr), "l"(gaddr));
}
__device__ __forceinline__ void cp_commit() { asm volatile("cp.async.commit_group;"); }
__device__ __forceinline__ void cp_wait1()  { asm volatile("cp.async.wait_group 1;"); }
__device__ __forceinline__ void cp_wait0()  { asm volatile("cp.async.wait_group 0;"); }

__global__ __launch_bounds__(NT, 1)
void dgcnn_kernel(const float* __restrict__ nf,
                  const int* __restrict__ src, const int* __restrict__ dst,
                  const int* __restrict__ degs,
                  const float* __restrict__ W0, const float* __restrict__ b0,
                  const float* __restrict__ W1, const float* __restrict__ b1,
                  const float* __restrict__ W2, const float* __restrict__ b2,
                  const float* __restrict__ W3, const float* __restrict__ b3,
                  const float* __restrict__ c1w, const float* __restrict__ c1b,
                  const float* __restrict__ c2w, const float* __restrict__ c2b,
                  const float* __restrict__ ow, const float* __restrict__ ob,
                  float* __restrict__ out)
{
    extern __shared__ float sm[];
    float* h1    = sm + OFF_H1;
    float* h2    = sm + OFF_H2;
    float* h3    = sm + OFF_H3;
    float* g     = sm + OFF_G;
    float* z4    = sm + OFF_Z4;
    float* invd  = sm + OFF_INVD;
    float* Ws0   = sm + OFF_WS0;
    float* Ws1   = sm + OFF_WS1;
    float* Ws2   = sm + OFF_WS2;
    float* bs    = sm + OFF_BS;
    float* scr   = sm + OFF_SCR;
    int*   offs  = (int*)(sm + OFF_OFFS);
    int*   cnt   = (int*)(sm + OFF_CNT);
    int*   elist = (int*)(sm + OFF_ELIST);

    const int b    = blockIdx.x;
    const int t    = threadIdx.x;
    const int w    = t >> 5;
    const int lane = t & 31;
    const int base = b * NPG_;

    // ---- init: degrees (padded to x8), zero row 256 of g, stage all weights ----
    int pdeg;
    {
        int d = degs[base + t];
        pdeg = (d + 7) & ~7;
        invd[t] = 1.0f / ((float)d + 1.0f);
        cnt[t] = d;
        g[256 * 32 + lane] = 0.f;
    }
    for (int i = t; i < FDIM * 32; i += NT) {
        int k = i >> 5, l = i & 31;
        Ws0[l * 132 + k] = W0[i];
    }
    for (int i = t; i < 1024; i += NT) { Ws1[i] = W1[i]; Ws2[i] = W2[i]; }
    if (t < 32) { bs[t] = b0[t]; bs[32 + t] = b1[t]; bs[64 + t] = b2[t]; }

    // ---- Hillis-Steele scan of padded degrees -> offs (exclusive) ----
    offs[t] = pdeg;
    __syncthreads();
#pragma unroll
    for (int d = 1; d < 256; d <<= 1) {
        int u = (t >= d) ? offs[t - d] : 0;
        __syncthreads();
        offs[t] += u;
        __syncthreads();
    }
    int inc = offs[t];
    int exc = inc - pdeg;
    __syncthreads();
    offs[t] = exc;
    if (t == 255) offs[256] = inc;
    __syncthreads();
    int fill_beg = exc + cnt[t];
    int fill_end = offs[t + 1];
    cnt[t] = exc;
    __syncthreads();

    // ---- build CSR of in-edges (values ls*32), pad with dummy 256*32 ----
    for (int i = t; i < EPG; i += NT) {
        int e  = b * EPG + i;
        int ls = src[e] - base;
        int ld = dst[e] - base;
        int pos = atomicAdd(&cnt[ld], 1);
        elist[pos] = ls << 5;
    }
    __syncthreads();
    for (int p = fill_beg; p < fill_end; p++) elist[p] = 256 << 5;
    __syncthreads();

    // ---- Layer 0 GEMM with cp.async double-buffered staging ----
    // 8 chunks of 32 nodes; buffer half = 4096 floats (16KB); 4 cp16/thread/chunk
    {
        const u32 scr_s = (u32)__cvta_generic_to_shared(scr);
        // issue chunk 0
        {
            const float* gsrc = nf + (size_t)base * FDIM;
#pragma unroll
            for (int q = 0; q < 4; q++) {
                int f4i = t + q * NT;          // float4 index within 1024
                cp16(scr_s + f4i * 16, gsrc + f4i * 4);
            }
            cp_commit();
        }
        for (int c = 0; c < 8; c++) {
            if (c + 1 < 8) {
                const float* gsrc = nf + (size_t)(base + (c + 1) * 32) * FDIM;
                u32 buf_s = scr_s + ((c + 1) & 1) * 4096 * 4;
#pragma unroll
                for (int q = 0; q < 4; q++) {
                    int f4i = t + q * NT;
                    cp16(buf_s + f4i * 16, gsrc + f4i * 4);
                }
                cp_commit();
                cp_wait1();
            } else {
                cp_wait0();
            }
            __syncthreads();

            const float* buf = scr + (c & 1) * 4096;
            float acc[4] = {0.f, 0.f, 0.f, 0.f};
            const float* wbase = Ws0 + lane * 132;
#pragma unroll 4
            for (int k0 = 0; k0 < FDIM; k0 += 4) {
                float4 wv = *(const float4*)(wbase + k0);
#pragma unroll
                for (int i = 0; i < 4; i++) {
                    float4 r = *(const float4*)(buf + (w * 4 + i) * FDIM + k0);
                    acc[i] = fmaf(r.x, wv.x, acc[i]);
                    acc[i] = fmaf(r.y, wv.y, acc[i]);
                    acc[i] = fmaf(r.z, wv.z, acc[i]);
                    acc[i] = fmaf(r.w, wv.w, acc[i]);
                }
            }
#pragma unroll
            for (int i = 0; i < 4; i++)
                g[(c * 32 + w * 4 + i) * 32 + lane] = acc[i];
            __syncthreads();
        }
    }

    // ---- Layer 0 aggregate + tanh -> h1 (8 edges per step) ----
#pragma unroll 1
    for (int nn = 0; nn < 32; nn++) {
        int n = w * 32 + nn;
        float acc = g[n * 32 + lane];
        int beg = offs[n], end = offs[n + 1];
        for (int j = beg; j < end; j += 8) {
            int4 ea = *(const int4*)(elist + j);
            int4 eb = *(const int4*)(elist + j + 4);
            float v0 = g[ea.x + lane], v1 = g[ea.y + lane];
            float v2 = g[ea.z + lane], v3 = g[ea.w + lane];
            float v4 = g[eb.x + lane], v5 = g[eb.y + lane];
            float v6 = g[eb.z + lane], v7 = g[eb.w + lane];
            acc += ((v0 + v1) + (v2 + v3)) + ((v4 + v5) + (v6 + v7));
        }
        h1[n * 32 + lane] = tanhf((acc + bs[lane]) * invd[n]);
    }
    __syncthreads();

    // ---- Layers 1,2 (32->32) ----
    {
        float* hin = h1;
        for (int L = 0; L < 2; L++) {
            const float* Wst = (L == 0) ? Ws1 : Ws2;
            float bv = bs[32 + L * 32 + lane];
            float* hout = (L == 0) ? h2 : h3;

            float wr[32];
#pragma unroll
            for (int k = 0; k < 32; k++) wr[k] = Wst[k * 32 + lane];
#pragma unroll 1
            for (int nn = 0; nn < 32; nn++) {
                int n = w * 32 + nn;
                const float* row = hin + n * 32;
                float acc = 0.f;
#pragma unroll
                for (int k = 0; k < 32; k += 4) {
                    float4 r4 = *(const float4*)(row + k);
                    acc = fmaf(r4.x, wr[k],     acc);
                    acc = fmaf(r4.y, wr[k + 1], acc);
                    acc = fmaf(r4.z, wr[k + 2], acc);
                    acc = fmaf(r4.w, wr[k + 3], acc);
                }
                g[n * 32 + lane] = acc;
            }
            __syncthreads();

#pragma unroll 1
            for (int nn = 0; nn < 32; nn++) {
                int n = w * 32 + nn;
                float acc = g[n * 32 + lane];
                int beg = offs[n], end = offs[n + 1];
                for (int j = beg; j < end; j += 8) {
                    int4 ea = *(const int4*)(elist + j);
                    int4 eb = *(const int4*)(elist + j + 4);
                    float v0 = g[ea.x + lane], v1 = g[ea.y + lane];
                    float v2 = g[ea.z + lane], v3 = g[ea.w + lane];
                    float v4 = g[eb.x + lane], v5 = g[eb.y + lane];
                    float v6 = g[eb.z + lane], v7 = g[eb.w + lane];
                    acc += ((v0 + v1) + (v2 + v3)) + ((v4 + v5) + (v6 + v7));
                }
                hout[n * 32 + lane] = tanhf((acc + bv) * invd[n]);
            }
            __syncthreads();
            hin = hout;
        }
    }

    // ---- Layer 3 (32->1) -> z4 ----
    {
        float* g1 = scr;                 // 257 entries, [256] = 0 dummy
        float w3r = W3[lane];
        float b3v = b3[0];
        if (t == 0) g1[256] = 0.f;
#pragma unroll 1
        for (int nn = 0; nn < 32; nn++) {
            int n = w * 32 + nn;
            float v = h3[n * 32 + lane] * w3r;
#pragma unroll
            for (int off = 16; off; off >>= 1)
                v += __shfl_xor_sync(0xffffffffu, v, off);
            if (lane == 0) g1[n] = v;
        }
        __syncthreads();
        {
            float acc = g1[t];
            int beg = offs[t], end = offs[t + 1];
            for (int j = beg; j < end; j += 8) {
                int4 ea = *(const int4*)(elist + j);
                int4 eb = *(const int4*)(elist + j + 4);
                acc += ((g1[ea.x >> 5] + g1[ea.y >> 5])
                      + (g1[ea.z >> 5] + g1[ea.w >> 5]))
                     + ((g1[eb.x >> 5] + g1[eb.y >> 5])
                      + (g1[eb.z >> 5] + g1[eb.w >> 5]));
            }
            z4[t] = tanhf((acc + b3v) * invd[t]);
        }
        __syncthreads();
    }

    // ---- sortpool: rank = #{j : v_j > v_i or (==, j<i)} ----
    int* selrow = cnt;
    {
        float v = z4[t];
        int r = 0;
#pragma unroll 4
        for (int j0 = 0; j0 < 256; j0 += 4) {
            float4 u4 = *(const float4*)(z4 + j0);
            r += (int)((u4.x > v) || (u4.x == v && (j0    ) < t));
            r += (int)((u4.y > v) || (u4.y == v && (j0 + 1) < t));
            r += (int)((u4.z > v) || (u4.z == v && (j0 + 2) < t));
            r += (int)((u4.w > v) || (u4.w == v && (j0 + 3) < t));
        }
        if (r < KTOP) selrow[r] = t;
    }
    __syncthreads();

    // ---- gather sp[30][97] ----
    float* sp = scr;
    for (int i = t; i < KTOP * DLAT; i += NT) {
        int k = i / DLAT, d = i - k * DLAT;
        int n = selrow[k];
        float v;
        if (d < 32)      v = h1[n * 32 + d];
        else if (d < 64) v = h2[n * 32 + d - 32];
        else if (d < 96) v = h3[n * 32 + d - 64];
        else             v = z4[n];
        sp[i] = v;
    }
    __syncthreads();

    // ---- conv1 + relu -> out1[16][30] ----
    float* out1 = scr + 3000;
    for (int i = t; i < C1_ * KTOP; i += NT) {
        int c = i & 15, k = i >> 4;
        float acc = c1b[c];
        const float* wr = c1w + c * DLAT;
        const float* sr = sp + k * DLAT;
        for (int d = 0; d < DLAT; d++) acc = fmaf(sr[d], wr[d], acc);
        out1[c * KTOP + k] = fmaxf(acc, 0.f);
    }
    __syncthreads();

    // ---- maxpool(2,2) -> pool[16][15] ----
    float* pool = scr + 3500;
    if (t < C1_ * 15) {
        int c = t / 15, tt = t - c * 15;
        pool[t] = fmaxf(out1[c * KTOP + 2 * tt], out1[c * KTOP + 2 * tt + 1]);
    }
    __syncthreads();

    // ---- conv2 + relu -> out2[32][11] (352 outputs -> strided loop) ----
    float* out2 = scr + 3800;
    for (int i = t; i < C2_ * T2_; i += NT) {
        int c2 = i / T2_, tt = i - c2 * T2_;
        float acc = c2b[c2];
#pragma unroll
        for (int c1 = 0; c1 < C1_; c1++) {
            const float* wv = c2w + (c2 * C1_ + c1) * 5;
            const float* pv = pool + c1 * 15 + tt;
#pragma unroll
            for (int j = 0; j < 5; j++) acc = fmaf(pv[j], wv[j], acc);
        }
        out2[i] = fmaxf(acc, 0.f);
    }
    __syncthreads();

    // ---- dense + relu ----
    if (w == 0) {
        float a0 = 0.f, a1 = 0.f;
        for (int i = lane; i < DENSE_; i += 32) {
            float x = out2[i];
            a0 = fmaf(x, ow[i * 2 + 0], a0);
            a1 = fmaf(x, ow[i * 2 + 1], a1);
        }
#pragma unroll
        for (int off = 16; off; off >>= 1) {
            a0 += __shfl_xor_sync(0xffffffffu, a0, off);
            a1 += __shfl_xor_sync(0xffffffffu, a1, off);
        }
        if (lane == 0) {
            out[b * 2 + 0] = fmaxf(a0 + ob[0], 0.f);
            out[b * 2 + 1] = fmaxf(a1 + ob[1], 0.f);
        }
    }
}

extern "C" void kernel_launch(void* const* d_in, const int* in_sizes, int n_in,
                              void* d_out, int out_size)
{
    int iSrc, iDst, iDeg, iW0, ib0, iW1, ib1, iW2, ib2, iW3, ib3;
    int ic1w, ic1b, ic2w, ic2b, iow, iob;
    if (n_in > 1 && in_sizes[1] == NGR * EPG) {
        iSrc = 1; iDst = 2; iDeg = 3;
        iW0 = 4;  ib0 = 5;  iW1 = 6;  ib1 = 7;
        iW2 = 8;  ib2 = 9;  iW3 = 10; ib3 = 11;
        ic1w = 12; ic1b = 13; ic2w = 14; ic2b = 15; iow = 16; iob = 17;
    } else {
        iW0 = 1;  ib0 = 2;  iW1 = 3;  ib1 = 4;
        iW2 = 5;  ib2 = 6;  iW3 = 7;  ib3 = 8;
        ic1w = 9; ic1b = 10; ic2w = 11; ic2b = 12; iow = 13; iob = 14;
        iSrc = 15; iDst = 16; iDeg = 17;
    }

    cudaFuncSetAttribute(dgcnn_kernel,
                         cudaFuncAttributeMaxDynamicSharedMemorySize, SMEM_BYTES);

    dgcnn_kernel<<<NGR, NT, SMEM_BYTES>>>(
        (const float*)d_in[0],
        (const int*)d_in[iSrc], (const int*)d_in[iDst], (const int*)d_in[iDeg],
        (const float*)d_in[iW0], (const float*)d_in[ib0],
        (const float*)d_in[iW1], (const float*)d_in[ib1],
        (const float*)d_in[iW2], (const float*)d_in[ib2],
        (const float*)d_in[iW3], (const float*)d_in[ib3],
        (const float*)d_in[ic1w], (const float*)d_in[ic1b],
        (const float*)d_in[ic2w], (const float*)d_in[ic2b],
        (const float*)d_in[iow], (const float*)d_in[iob],
        (float*)d_out);
}

// round 8
// speedup vs baseline: 1.2739x; 1.2739x over previous
#include <cuda_runtime.h>
#include <math.h>

#define NGR    256
#define NPG_   256
#define FDIM   128
#define EPG    4096
#define DLAT   97
#define KTOP   30
#define C1_    16
#define C2_    32
#define T2_    11
#define DENSE_ 352
#define NT     256

typedef unsigned int   u32;
typedef unsigned short u16;

// h1 spill buffer (gathered back at sortpool) — static device global, no allocation
__device__ float h1g_buf[NGR * NPG_ * 32];   // 8MB

// shared layout (float units) — total 28292 floats = 113168 B  (fits 2 CTAs/SM)
#define OFF_A     0        // 8192  : h1 (L0 agg out) -> h3 (L2 agg out)
#define OFF_B     8192     // 8224  : g (257 rows x 32; row 256 = zeros); later g1 + conv scratch
#define OFF_C     16416    // 8192  : Ws0 overlay (first 4224) during L0 -> h2 (L1 agg out)
#define OFF_Z4    24608    // 256
#define OFF_INVD  24864    // 256
#define OFF_BS    25120    // 96 (b0,b1,b2)
#define OFF_OFFS  25216    // 257 ints
#define OFF_CNT   25473    // 256 ints
#define OFF_ELIST 25732    // 5120 u16 = 2560 floats (16B aligned)
#define SM_FLOATS 28292
static const int SMEM_BYTES = SM_FLOATS * 4;

__global__ __launch_bounds__(NT, 2)
void dgcnn_kernel(const float* __restrict__ nf,
                  const int* __restrict__ src, const int* __restrict__ dst,
                  const int* __restrict__ degs,
                  const float* __restrict__ W0, const float* __restrict__ b0,
                  const float* __restrict__ W1, const float* __restrict__ b1,
                  const float* __restrict__ W2, const float* __restrict__ b2,
                  const float* __restrict__ W3, const float* __restrict__ b3,
                  const float* __restrict__ c1w, const float* __restrict__ c1b,
                  const float* __restrict__ c2w, const float* __restrict__ c2b,
                  const float* __restrict__ ow, const float* __restrict__ ob,
                  float* __restrict__ out)
{
    extern __shared__ float sm[];
    float* A     = sm + OFF_A;
    float* B     = sm + OFF_B;
    float* C     = sm + OFF_C;
    float* z4    = sm + OFF_Z4;
    float* invd  = sm + OFF_INVD;
    float* bs    = sm + OFF_BS;
    int*   offs  = (int*)(sm + OFF_OFFS);
    int*   cnt   = (int*)(sm + OFF_CNT);
    u16*   elist = (u16*)(sm + OFF_ELIST);

    const int b    = blockIdx.x;
    const int t    = threadIdx.x;
    const int w    = t >> 5;
    const int lane = t & 31;
    const int base = b * NPG_;

    // ---- init: degrees (pad x4), zero B dummy row, stage W0 (transposed, pitch 132) in C ----
    int pdeg;
    {
        int d = degs[base + t];
        pdeg = (d + 3) & ~3;
        invd[t] = 1.0f / ((float)d + 1.0f);
        cnt[t] = d;
        B[256 * 32 + lane] = 0.f;
    }
    for (int i = t; i < FDIM * 32; i += NT) {
        int k = i >> 5, l = i & 31;
        C[l * 132 + k] = W0[i];
    }
    if (t < 32) { bs[t] = b0[t]; bs[32 + t] = b1[t]; bs[64 + t] = b2[t]; }

    // ---- Hillis-Steele scan of padded degrees -> offs (exclusive) ----
    offs[t] = pdeg;
    __syncthreads();
#pragma unroll
    for (int d = 1; d < 256; d <<= 1) {
        int u = (t >= d) ? offs[t - d] : 0;
        __syncthreads();
        offs[t] += u;
        __syncthreads();
    }
    int inc = offs[t];
    int exc = inc - pdeg;
    __syncthreads();
    offs[t] = exc;
    if (t == 255) offs[256] = inc;
    __syncthreads();
    int fill_beg = exc + cnt[t];
    int fill_end = offs[t + 1];
    cnt[t] = exc;
    __syncthreads();

    // ---- build CSR of in-edges: values are (ls << 5) as u16; pad with dummy 8192 ----
    for (int i = t; i < EPG; i += NT) {
        int e  = b * EPG + i;
        int ls = src[e] - base;
        int ld = dst[e] - base;
        int pos = atomicAdd(&cnt[ld], 1);
        elist[pos] = (u16)(ls << 5);
    }
    __syncthreads();
    for (int p = fill_beg; p < fill_end; p++) elist[p] = (u16)(256 << 5);
    __syncthreads();

    // ---- Layer 0 GEMM: B = nf @ W0, direct broadcast LDG from global ----
    // warp w owns nodes w*32..w*32+31, 4 groups of 8 (acc[8])
    {
        const float* wbase = C + lane * 132;
        for (int grp = 0; grp < 4; grp++) {
            int n0 = w * 32 + grp * 8;
            const float* nfb = nf + (size_t)(base + n0) * FDIM;
            float acc[8] = {0.f,0.f,0.f,0.f,0.f,0.f,0.f,0.f};
#pragma unroll 4
            for (int k0 = 0; k0 < FDIM; k0 += 4) {
                float4 wv = *(const float4*)(wbase + k0);
#pragma unroll
                for (int i = 0; i < 8; i++) {
                    float4 r = __ldg((const float4*)(nfb + i * FDIM + k0));
                    acc[i] = fmaf(r.x, wv.x, acc[i]);
                    acc[i] = fmaf(r.y, wv.y, acc[i]);
                    acc[i] = fmaf(r.z, wv.z, acc[i]);
                    acc[i] = fmaf(r.w, wv.w, acc[i]);
                }
            }
#pragma unroll
            for (int i = 0; i < 8; i++)
                B[(n0 + i) * 32 + lane] = acc[i];
        }
    }
    __syncthreads();

    // ---- Layer 0 aggregate + tanh -> A (= h1) ----
#pragma unroll 1
    for (int nn = 0; nn < 32; nn++) {
        int n = w * 32 + nn;
        float acc = B[n * 32 + lane];
        int beg = offs[n], end = offs[n + 1];
        for (int j = beg; j < end; j += 4) {
            uint2 e2 = *(const uint2*)(elist + j);
            int i0 = e2.x & 0xffff, i1 = e2.x >> 16;
            int i2 = e2.y & 0xffff, i3 = e2.y >> 16;
            acc += (B[i0 + lane] + B[i1 + lane]) + (B[i2 + lane] + B[i3 + lane]);
        }
        A[n * 32 + lane] = tanhf((acc + bs[lane]) * invd[n]);
    }
    __syncthreads();

    // ---- stream h1 (A) to global for later gather ----
    {
        float4* dst4 = (float4*)(h1g_buf + (size_t)base * 32);
        const float4* src4 = (const float4*)A;
        for (int i = t; i < NPG_ * 32 / 4; i += NT) dst4[i] = src4[i];
    }
    // no sync needed yet: L1 GEMM only reads A

    // ---- Layers 1,2 (32->32); weights straight from global into regs ----
    {
        float* hin = A;
        for (int L = 0; L < 2; L++) {
            const float* Wg = (L == 0) ? W1 : W2;
            float bv = bs[32 + L * 32 + lane];
            float* hout = (L == 0) ? C : A;   // L1 -> C (h2), L2 -> A (h3)

            float wr[32];
#pragma unroll
            for (int k = 0; k < 32; k++) wr[k] = __ldg(Wg + k * 32 + lane);
#pragma unroll 1
            for (int nn = 0; nn < 32; nn++) {
                int n = w * 32 + nn;
                const float* row = hin + n * 32;
                float acc = 0.f;
#pragma unroll
                for (int k = 0; k < 32; k += 4) {
                    float4 r4 = *(const float4*)(row + k);
                    acc = fmaf(r4.x, wr[k],     acc);
                    acc = fmaf(r4.y, wr[k + 1], acc);
                    acc = fmaf(r4.z, wr[k + 2], acc);
                    acc = fmaf(r4.w, wr[k + 3], acc);
                }
                B[n * 32 + lane] = acc;
            }
            __syncthreads();

#pragma unroll 1
            for (int nn = 0; nn < 32; nn++) {
                int n = w * 32 + nn;
                float acc = B[n * 32 + lane];
                int beg = offs[n], end = offs[n + 1];
                for (int j = beg; j < end; j += 4) {
                    uint2 e2 = *(const uint2*)(elist + j);
                    int i0 = e2.x & 0xffff, i1 = e2.x >> 16;
                    int i2 = e2.y & 0xffff, i3 = e2.y >> 16;
                    acc += (B[i0 + lane] + B[i1 + lane]) + (B[i2 + lane] + B[i3 + lane]);
                }
                hout[n * 32 + lane] = tanhf((acc + bv) * invd[n]);
            }
            __syncthreads();
            hin = hout;
        }
    }

    // ---- Layer 3 (32->1) -> z4 ; g1 lives compactly in B[0..256] (B dead now) ----
    {
        float* g1 = B;
        float w3r = __ldg(W3 + lane);
        float b3v = __ldg(b3);
        if (t == 0) g1[256] = 0.f;
#pragma unroll 1
        for (int nn = 0; nn < 32; nn++) {
            int n = w * 32 + nn;
            float v = A[n * 32 + lane] * w3r;   // A = h3
#pragma unroll
            for (int off = 16; off; off >>= 1)
                v += __shfl_xor_sync(0xffffffffu, v, off);
            if (lane == 0) g1[n] = v;
        }
        __syncthreads();
        {
            float acc = g1[t];
            int beg = offs[t], end = offs[t + 1];
            for (int j = beg; j < end; j += 4) {
                uint2 e2 = *(const uint2*)(elist + j);
                acc += (g1[(e2.x & 0xffff) >> 5] + g1[(e2.x >> 16) >> 5])
                     + (g1[(e2.y & 0xffff) >> 5] + g1[(e2.y >> 16) >> 5]);
            }
            z4[t] = tanhf((acc + b3v) * invd[t]);
        }
        __syncthreads();
    }

    // ---- sortpool: rank = #{j : v_j > v_i or (==, j<i)} ----
    int* selrow = cnt;
    {
        float v = z4[t];
        int r = 0;
#pragma unroll 4
        for (int j0 = 0; j0 < 256; j0 += 4) {
            float4 u4 = *(const float4*)(z4 + j0);
            r += (int)((u4.x > v) || (u4.x == v && (j0    ) < t));
            r += (int)((u4.y > v) || (u4.y == v && (j0 + 1) < t));
            r += (int)((u4.z > v) || (u4.z == v && (j0 + 2) < t));
            r += (int)((u4.w > v) || (u4.w == v && (j0 + 3) < t));
        }
        if (r < KTOP) selrow[r] = t;
    }
    __syncthreads();

    // ---- gather sp[30][97]: h1 from global, h2 from C, h3 from A, z4 ----
    float* sp = B + 512;
    for (int i = t; i < KTOP * DLAT; i += NT) {
        int k = i / DLAT, d = i - k * DLAT;
        int n = selrow[k];
        float v;
        if (d < 32)      v = h1g_buf[(size_t)(base + n) * 32 + d];
        else if (d < 64) v = C[n * 32 + d - 32];
        else if (d < 96) v = A[n * 32 + d - 64];
        else             v = z4[n];
        sp[i] = v;
    }
    __syncthreads();

    // ---- conv1 + relu -> out1[16][30] ----
    float* out1 = B + 3600;
    for (int i = t; i < C1_ * KTOP; i += NT) {
        int c = i & 15, k = i >> 4;
        float acc = c1b[c];
        const float* wr = c1w + c * DLAT;
        const float* sr = sp + k * DLAT;
        for (int d = 0; d < DLAT; d++) acc = fmaf(sr[d], wr[d], acc);
        out1[c * KTOP + k] = fmaxf(acc, 0.f);
    }
    __syncthreads();

    // ---- maxpool(2,2) -> pool[16][15] ----
    float* pool = B + 4200;
    if (t < C1_ * 15) {
        int c = t / 15, tt = t - c * 15;
        pool[t] = fmaxf(out1[c * KTOP + 2 * tt], out1[c * KTOP + 2 * tt + 1]);
    }
    __syncthreads();

    // ---- conv2 + relu -> out2[32][11]  (352 outputs -> strided loop) ----
    float* out2 = B + 4500;
    for (int i = t; i < C2_ * T2_; i += NT) {
        int c2 = i / T2_, tt = i - c2 * T2_;
        float acc = c2b[c2];
#pragma unroll
        for (int c1 = 0; c1 < C1_; c1++) {
            const float* wv = c2w + (c2 * C1_ + c1) * 5;
            const float* pv = pool + c1 * 15 + tt;
#pragma unroll
            for (int j = 0; j < 5; j++) acc = fmaf(pv[j], wv[j], acc);
        }
        out2[i] = fmaxf(acc, 0.f);
    }
    __syncthreads();

    // ---- dense [352]x[352,2] + relu ----
    if (w == 0) {
        float a0 = 0.f, a1 = 0.f;
        for (int i = lane; i < DENSE_; i += 32) {
            float x = out2[i];
            a0 = fmaf(x, ow[i * 2 + 0], a0);
            a1 = fmaf(x, ow[i * 2 + 1], a1);
        }
#pragma unroll
        for (int off = 16; off; off >>= 1) {
            a0 += __shfl_xor_sync(0xffffffffu, a0, off);
            a1 += __shfl_xor_sync(0xffffffffu, a1, off);
        }
        if (lane == 0) {
            out[b * 2 + 0] = fmaxf(a0 + ob[0], 0.f);
            out[b * 2 + 1] = fmaxf(a1 + ob[1], 0.f);
        }
    }
}

extern "C" void kernel_launch(void* const* d_in, const int* in_sizes, int n_in,
                              void* d_out, int out_size)
{
    int iSrc, iDst, iDeg, iW0, ib0, iW1, ib1, iW2, ib2, iW3, ib3;
    int ic1w, ic1b, ic2w, ic2b, iow, iob;
    if (n_in > 1 && in_sizes[1] == NGR * EPG) {
        iSrc = 1; iDst = 2; iDeg = 3;
        iW0 = 4;  ib0 = 5;  iW1 = 6;  ib1 = 7;
        iW2 = 8;  ib2 = 9;  iW3 = 10; ib3 = 11;
        ic1w = 12; ic1b = 13; ic2w = 14; ic2b = 15; iow = 16; iob = 17;
    } else {
        iW0 = 1;  ib0 = 2;  iW1 = 3;  ib1 = 4;
        iW2 = 5;  ib2 = 6;  iW3 = 7;  ib3 = 8;
        ic1w = 9; ic1b = 10; ic2w = 11; ic2b = 12; iow = 13; iob = 14;
        iSrc = 15; iDst = 16; iDeg = 17;
    }

    cudaFuncSetAttribute(dgcnn_kernel,
                         cudaFuncAttributeMaxDynamicSharedMemorySize, SMEM_BYTES);

    dgcnn_kernel<<<NGR, NT, SMEM_BYTES>>>(
        (const float*)d_in[0],
        (const int*)d_in[iSrc], (const int*)d_in[iDst], (const int*)d_in[iDeg],
        (const float*)d_in[iW0], (const float*)d_in[ib0],
        (const float*)d_in[iW1], (const float*)d_in[ib1],
        (const float*)d_in[iW2], (const float*)d_in[ib2],
        (const float*)d_in[iW3], (const float*)d_in[ib3],
        (const float*)d_in[ic1w], (const float*)d_in[ic1b],
        (const float*)d_in[ic2w], (const float*)d_in[ic2b],
        (const float*)d_in[iow], (const float*)d_in[iob],
        (float*)d_out);
}

// round 9
// speedup vs baseline: 1.2769x; 1.0023x over previous
#include <cuda_runtime.h>
#include <math.h>

#define NGR    256
#define NPG_   256
#define FDIM   128
#define EPG    4096
#define DLAT   97
#define KTOP   30
#define C1_    16
#define C2_    32
#define T2_    11
#define DENSE_ 352
#define NT     384
#define NW     12

typedef unsigned int   u32;
typedef unsigned short u16;

// h1 spill buffer (gathered back at sortpool) — static device global
__device__ float h1g_buf[NGR * NPG_ * 32];   // 8MB

// shared layout (float units) — total 28292 floats = 113168 B (2 CTAs/SM)
#define OFF_A     0        // 8192 : h1 -> h3
#define OFF_B     8192     // 8224 : g (257x32, row 256 zeros); later g1 + conv scratch
#define OFF_C     16416    // 8192 : W0 overlay (4224) during L0 -> h2
#define OFF_Z4    24608    // 256
#define OFF_INVD  24864    // 256
#define OFF_BS    25120    // 96
#define OFF_OFFS  25216    // 257 ints
#define OFF_CNT   25473    // 256 ints
#define OFF_ELIST 25732    // 5120 u16 = 2560 floats
#define SM_FLOATS 28292
static const int SMEM_BYTES = SM_FLOATS * 4;

__global__ __launch_bounds__(NT, 2)
void dgcnn_kernel(const float* __restrict__ nf,
                  const int* __restrict__ src, const int* __restrict__ dst,
                  const int* __restrict__ degs,
                  const float* __restrict__ W0, const float* __restrict__ b0,
                  const float* __restrict__ W1, const float* __restrict__ b1,
                  const float* __restrict__ W2, const float* __restrict__ b2,
                  const float* __restrict__ W3, const float* __restrict__ b3,
                  const float* __restrict__ c1w, const float* __restrict__ c1b,
                  const float* __restrict__ c2w, const float* __restrict__ c2b,
                  const float* __restrict__ ow, const float* __restrict__ ob,
                  float* __restrict__ out)
{
    extern __shared__ float sm[];
    float* A     = sm + OFF_A;
    float* B     = sm + OFF_B;
    float* C     = sm + OFF_C;
    float* z4    = sm + OFF_Z4;
    float* invd  = sm + OFF_INVD;
    float* bs    = sm + OFF_BS;
    int*   offs  = (int*)(sm + OFF_OFFS);
    int*   cnt   = (int*)(sm + OFF_CNT);
    u16*   elist = (u16*)(sm + OFF_ELIST);

    const int b    = blockIdx.x;
    const int t    = threadIdx.x;
    const int w    = t >> 5;
    const int lane = t & 31;
    const int base = b * NPG_;

    // ---- init ----
    int pdeg = 0;
    if (t < 256) {
        int d = degs[base + t];
        pdeg = (d + 3) & ~3;
        invd[t] = 1.0f / ((float)d + 1.0f);
        cnt[t] = d;
    }
    B[256 * 32 + lane] = 0.f;   // dummy row (all warps, idempotent)
    for (int i = t; i < FDIM * 32; i += NT) {
        int k = i >> 5, l = i & 31;
        C[l * 132 + k] = W0[i];
    }
    if (t < 32) { bs[t] = b0[t]; bs[32 + t] = b1[t]; bs[64 + t] = b2[t]; }

    // ---- scan of padded degrees -> offs (exclusive) ----
    if (t < 256) offs[t] = pdeg;
    __syncthreads();
#pragma unroll
    for (int d = 1; d < 256; d <<= 1) {
        int u = (t < 256 && t >= d) ? offs[t - d] : 0;
        __syncthreads();
        if (t < 256) offs[t] += u;
        __syncthreads();
    }
    int fill_beg = 0, fill_end = 0;
    if (t < 256) {
        int inc = offs[t];
        int exc = inc - pdeg;
        __syncthreads();
        offs[t] = exc;
        if (t == 255) offs[256] = inc;
        fill_beg = exc + cnt[t];
    } else {
        __syncthreads();
    }
    __syncthreads();
    if (t < 256) {
        fill_end = offs[t + 1];
        cnt[t] = offs[t];
    }
    __syncthreads();

    // ---- build CSR (values ls<<5 as u16), pad with dummy 256<<5 ----
    for (int i = t; i < EPG; i += NT) {
        int e  = b * EPG + i;
        int ls = src[e] - base;
        int ld = dst[e] - base;
        int pos = atomicAdd(&cnt[ld], 1);
        elist[pos] = (u16)(ls << 5);
    }
    __syncthreads();
    for (int p = fill_beg; p < fill_end; p++) elist[p] = (u16)(256 << 5);
    __syncthreads();

    // ---- Layer 0 GEMM: B = nf @ W0 (4-node groups, warp-strided) ----
    {
        const float* wbase = C + lane * 132;
        for (int gid = w; gid < 64; gid += NW) {
            int n0 = gid * 4;
            const float* nfb = nf + (size_t)(base + n0) * FDIM;
            float acc[4] = {0.f, 0.f, 0.f, 0.f};
#pragma unroll 4
            for (int k0 = 0; k0 < FDIM; k0 += 4) {
                float4 wv = *(const float4*)(wbase + k0);
#pragma unroll
                for (int i = 0; i < 4; i++) {
                    float4 r = __ldg((const float4*)(nfb + i * FDIM + k0));
                    acc[i] = fmaf(r.x, wv.x, acc[i]);
                    acc[i] = fmaf(r.y, wv.y, acc[i]);
                    acc[i] = fmaf(r.z, wv.z, acc[i]);
                    acc[i] = fmaf(r.w, wv.w, acc[i]);
                }
            }
#pragma unroll
            for (int i = 0; i < 4; i++)
                B[(n0 + i) * 32 + lane] = acc[i];
        }
    }
    __syncthreads();

    // ---- Layer 0 aggregate + tanh -> A (= h1), warp-strided nodes ----
    for (int n = w; n < 256; n += NW) {
        float acc = B[n * 32 + lane];
        int beg = offs[n], end = offs[n + 1];
        for (int j = beg; j < end; j += 4) {
            uint2 e2 = *(const uint2*)(elist + j);
            int i0 = e2.x & 0xffff, i1 = e2.x >> 16;
            int i2 = e2.y & 0xffff, i3 = e2.y >> 16;
            acc += (B[i0 + lane] + B[i1 + lane]) + (B[i2 + lane] + B[i3 + lane]);
        }
        A[n * 32 + lane] = tanhf((acc + bs[lane]) * invd[n]);
    }
    __syncthreads();

    // ---- stream h1 to global (overlaps with L1 GEMM reads of A) ----
    {
        float4* dst4 = (float4*)(h1g_buf + (size_t)base * 32);
        const float4* src4 = (const float4*)A;
        for (int i = t; i < NPG_ * 32 / 4; i += NT) dst4[i] = src4[i];
    }

    // ---- Layers 1,2 (32->32); weights from global into regs ----
    {
        float* hin = A;
        for (int L = 0; L < 2; L++) {
            const float* Wg = (L == 0) ? W1 : W2;
            float bv = bs[32 + L * 32 + lane];
            float* hout = (L == 0) ? C : A;   // L1 -> C (h2), L2 -> A (h3)

            float wr[32];
#pragma unroll
            for (int k = 0; k < 32; k++) wr[k] = __ldg(Wg + k * 32 + lane);
            for (int n = w; n < 256; n += NW) {
                const float* row = hin + n * 32;
                float acc = 0.f;
#pragma unroll
                for (int k = 0; k < 32; k += 4) {
                    float4 r4 = *(const float4*)(row + k);
                    acc = fmaf(r4.x, wr[k],     acc);
                    acc = fmaf(r4.y, wr[k + 1], acc);
                    acc = fmaf(r4.z, wr[k + 2], acc);
                    acc = fmaf(r4.w, wr[k + 3], acc);
                }
                B[n * 32 + lane] = acc;
            }
            __syncthreads();

            for (int n = w; n < 256; n += NW) {
                float acc = B[n * 32 + lane];
                int beg = offs[n], end = offs[n + 1];
                for (int j = beg; j < end; j += 4) {
                    uint2 e2 = *(const uint2*)(elist + j);
                    int i0 = e2.x & 0xffff, i1 = e2.x >> 16;
                    int i2 = e2.y & 0xffff, i3 = e2.y >> 16;
                    acc += (B[i0 + lane] + B[i1 + lane]) + (B[i2 + lane] + B[i3 + lane]);
                }
                hout[n * 32 + lane] = tanhf((acc + bv) * invd[n]);
            }
            __syncthreads();
            hin = hout;
        }
    }

    // ---- Layer 3 (32->1) -> z4 ; g1 in B[0..256] ----
    {
        float* g1 = B;
        float w3r = __ldg(W3 + lane);
        float b3v = __ldg(b3);
        if (t == 0) g1[256] = 0.f;
        for (int n = w; n < 256; n += NW) {
            float v = A[n * 32 + lane] * w3r;   // A = h3
#pragma unroll
            for (int off = 16; off; off >>= 1)
                v += __shfl_xor_sync(0xffffffffu, v, off);
            if (lane == 0) g1[n] = v;
        }
        __syncthreads();
        if (t < 256) {
            float acc = g1[t];
            int beg = offs[t], end = offs[t + 1];
            for (int j = beg; j < end; j += 4) {
                uint2 e2 = *(const uint2*)(elist + j);
                acc += (g1[(e2.x & 0xffff) >> 5] + g1[(e2.x >> 16) >> 5])
                     + (g1[(e2.y & 0xffff) >> 5] + g1[(e2.y >> 16) >> 5]);
            }
            z4[t] = tanhf((acc + b3v) * invd[t]);
        }
        __syncthreads();
    }

    // ---- sortpool rank selection ----
    int* selrow = cnt;
    if (t < 256) {
        float v = z4[t];
        int r = 0;
#pragma unroll 4
        for (int j0 = 0; j0 < 256; j0 += 4) {
            float4 u4 = *(const float4*)(z4 + j0);
            r += (int)((u4.x > v) || (u4.x == v && (j0    ) < t));
            r += (int)((u4.y > v) || (u4.y == v && (j0 + 1) < t));
            r += (int)((u4.z > v) || (u4.z == v && (j0 + 2) < t));
            r += (int)((u4.w > v) || (u4.w == v && (j0 + 3) < t));
        }
        if (r < KTOP) selrow[r] = t;
    }
    __syncthreads();

    // ---- gather sp[30][97] ----
    float* sp = B + 512;
    for (int i = t; i < KTOP * DLAT; i += NT) {
        int k = i / DLAT, d = i - k * DLAT;
        int n = selrow[k];
        float v;
        if (d < 32)      v = h1g_buf[(size_t)(base + n) * 32 + d];
        else if (d < 64) v = C[n * 32 + d - 32];
        else if (d < 96) v = A[n * 32 + d - 64];
        else             v = z4[n];
        sp[i] = v;
    }
    __syncthreads();

    // ---- conv1 + relu -> out1[16][30] ----
    float* out1 = B + 3600;
    for (int i = t; i < C1_ * KTOP; i += NT) {
        int c = i & 15, k = i >> 4;
        float acc = c1b[c];
        const float* wr = c1w + c * DLAT;
        const float* sr = sp + k * DLAT;
        for (int d = 0; d < DLAT; d++) acc = fmaf(sr[d], wr[d], acc);
        out1[c * KTOP + k] = fmaxf(acc, 0.f);
    }
    __syncthreads();

    // ---- maxpool(2,2) -> pool[16][15] ----
    float* pool = B + 4200;
    if (t < C1_ * 15) {
        int c = t / 15, tt = t - c * 15;
        pool[t] = fmaxf(out1[c * KTOP + 2 * tt], out1[c * KTOP + 2 * tt + 1]);
    }
    __syncthreads();

    // ---- conv2 + relu -> out2[32][11] ----
    float* out2 = B + 4500;
    for (int i = t; i < C2_ * T2_; i += NT) {
        int c2 = i / T2_, tt = i - c2 * T2_;
        float acc = c2b[c2];
#pragma unroll
        for (int c1 = 0; c1 < C1_; c1++) {
            const float* wv = c2w + (c2 * C1_ + c1) * 5;
            const float* pv = pool + c1 * 15 + tt;
#pragma unroll
            for (int j = 0; j < 5; j++) acc = fmaf(pv[j], wv[j], acc);
        }
        out2[i] = fmaxf(acc, 0.f);
    }
    __syncthreads();

    // ---- dense [352]x[352,2] + relu ----
    if (w == 0) {
        float a0 = 0.f, a1 = 0.f;
        for (int i = lane; i < DENSE_; i += 32) {
            float x = out2[i];
            a0 = fmaf(x, ow[i * 2 + 0], a0);
            a1 = fmaf(x, ow[i * 2 + 1], a1);
        }
#pragma unroll
        for (int off = 16; off; off >>= 1) {
            a0 += __shfl_xor_sync(0xffffffffu, a0, off);
            a1 += __shfl_xor_sync(0xffffffffu, a1, off);
        }
        if (lane == 0) {
            out[b * 2 + 0] = fmaxf(a0 + ob[0], 0.f);
            out[b * 2 + 1] = fmaxf(a1 + ob[1], 0.f);
        }
    }
}

extern "C" void kernel_launch(void* const* d_in, const int* in_sizes, int n_in,
                              void* d_out, int out_size)
{
    int iSrc, iDst, iDeg, iW0, ib0, iW1, ib1, iW2, ib2, iW3, ib3;
    int ic1w, ic1b, ic2w, ic2b, iow, iob;
    if (n_in > 1 && in_sizes[1] == NGR * EPG) {
        iSrc = 1; iDst = 2; iDeg = 3;
        iW0 = 4;  ib0 = 5;  iW1 = 6;  ib1 = 7;
        iW2 = 8;  ib2 = 9;  iW3 = 10; ib3 = 11;
        ic1w = 12; ic1b = 13; ic2w = 14; ic2b = 15; iow = 16; iob = 17;
    } else {
        iW0 = 1;  ib0 = 2;  iW1 = 3;  ib1 = 4;
        iW2 = 5;  ib2 = 6;  iW3 = 7;  ib3 = 8;
        ic1w = 9; ic1b = 10; ic2w = 11; ic2b = 12; iow = 13; iob = 14;
        iSrc = 15; iDst = 16; iDeg = 17;
    }

    cudaFuncSetAttribute(dgcnn_kernel,
                         cudaFuncAttributeMaxDynamicSharedMemorySize, SMEM_BYTES);

    dgcnn_kernel<<<NGR, NT, SMEM_BYTES>>>(
        (const float*)d_in[0],
        (const int*)d_in[iSrc], (const int*)d_in[iDst], (const int*)d_in[iDeg],
        (const float*)d_in[iW0], (const float*)d_in[ib0],
        (const float*)d_in[iW1], (const float*)d_in[ib1],
        (const float*)d_in[iW2], (const float*)d_in[ib2],
        (const float*)d_in[iW3], (const float*)d_in[ib3],
        (const float*)d_in[ic1w], (const float*)d_in[ic1b],
        (const float*)d_in[ic2w], (const float*)d_in[ic2b],
        (const float*)d_in[iow], (const float*)d_in[iob],
        (float*)d_out);
}

// round 10
// speedup vs baseline: 1.2814x; 1.0036x over previous
#include <cuda_runtime.h>
#include <math.h>

#define NGR    256
#define NPG_   256
#define FDIM   128
#define EPG    4096
#define DLAT   97
#define KTOP   30
#define C1_    16
#define C2_    32
#define T2_    11
#define DENSE_ 352
#define NT     384
#define NW     12

typedef unsigned int   u32;
typedef unsigned short u16;

// h1 spill buffer (gathered back at sortpool) — static device global
__device__ float h1g_buf[NGR * NPG_ * 32];   // 8MB

// shared layout (float units) — total 28292 floats = 113168 B (2 CTAs/SM)
#define OFF_A     0        // 8192 : h1 -> h3
#define OFF_B     8192     // 8224 : g (257x32, row 256 zeros); later g1 + conv scratch
#define OFF_C     16416    // 8192 : W0 overlay (4224) during L0 -> h2
#define OFF_Z4    24608    // 256
#define OFF_INVD  24864    // 256
#define OFF_BS    25120    // 96
#define OFF_OFFS  25216    // 257 ints
#define OFF_CNT   25473    // 256 ints
#define OFF_ELIST 25732    // 5120 u16 = 2560 floats
#define SM_FLOATS 28292
static const int SMEM_BYTES = SM_FLOATS * 4;

// aggregate 4 edges with prefetched indices; cur holds indices (pre-shifted by 5)
__device__ __forceinline__ float agg4(const float* __restrict__ Bp, uint2 cur, int lane) {
    int i0 = (int)(cur.x & 0xffffu), i1 = (int)(cur.x >> 16);
    int i2 = (int)(cur.y & 0xffffu), i3 = (int)(cur.y >> 16);
    return (Bp[i0 + lane] + Bp[i1 + lane]) + (Bp[i2 + lane] + Bp[i3 + lane]);
}

__global__ __launch_bounds__(NT, 2)
void dgcnn_kernel(const float* __restrict__ nf,
                  const int* __restrict__ src, const int* __restrict__ dst,
                  const int* __restrict__ degs,
                  const float* __restrict__ W0, const float* __restrict__ b0,
                  const float* __restrict__ W1, const float* __restrict__ b1,
                  const float* __restrict__ W2, const float* __restrict__ b2,
                  const float* __restrict__ W3, const float* __restrict__ b3,
                  const float* __restrict__ c1w, const float* __restrict__ c1b,
                  const float* __restrict__ c2w, const float* __restrict__ c2b,
                  const float* __restrict__ ow, const float* __restrict__ ob,
                  float* __restrict__ out)
{
    extern __shared__ float sm[];
    float* A     = sm + OFF_A;
    float* B     = sm + OFF_B;
    float* C     = sm + OFF_C;
    float* z4    = sm + OFF_Z4;
    float* invd  = sm + OFF_INVD;
    float* bs    = sm + OFF_BS;
    int*   offs  = (int*)(sm + OFF_OFFS);
    int*   cnt   = (int*)(sm + OFF_CNT);
    u16*   elist = (u16*)(sm + OFF_ELIST);

    const int b    = blockIdx.x;
    const int t    = threadIdx.x;
    const int w    = t >> 5;
    const int lane = t & 31;
    const int base = b * NPG_;

    // ---- init ----
    int pdeg = 0;
    if (t < 256) {
        int d = degs[base + t];
        pdeg = (d + 3) & ~3;
        invd[t] = 1.0f / ((float)d + 1.0f);
        cnt[t] = d;
    }
    B[256 * 32 + lane] = 0.f;   // dummy row
    for (int i = t; i < FDIM * 32; i += NT) {
        int k = i >> 5, l = i & 31;
        C[l * 132 + k] = W0[i];
    }
    if (t < 32) { bs[t] = b0[t]; bs[32 + t] = b1[t]; bs[64 + t] = b2[t]; }

    // ---- scan of padded degrees -> offs (exclusive) ----
    if (t < 256) offs[t] = pdeg;
    __syncthreads();
#pragma unroll
    for (int d = 1; d < 256; d <<= 1) {
        int u = (t < 256 && t >= d) ? offs[t - d] : 0;
        __syncthreads();
        if (t < 256) offs[t] += u;
        __syncthreads();
    }
    int fill_beg = 0, fill_end = 0;
    if (t < 256) {
        int inc = offs[t];
        int exc = inc - pdeg;
        __syncthreads();
        offs[t] = exc;
        if (t == 255) offs[256] = inc;
        fill_beg = exc + cnt[t];
    } else {
        __syncthreads();
    }
    __syncthreads();
    if (t < 256) {
        fill_end = offs[t + 1];
        cnt[t] = offs[t];
    }
    __syncthreads();

    // ---- build CSR (values ls<<5 as u16), 4 edges per iteration ----
    for (int i = t * 4; i < EPG; i += NT * 4) {
        int4 s4 = *(const int4*)(src + b * EPG + i);
        int4 d4 = *(const int4*)(dst + b * EPG + i);
        int p0 = atomicAdd(&cnt[d4.x - base], 1); elist[p0] = (u16)((s4.x - base) << 5);
        int p1 = atomicAdd(&cnt[d4.y - base], 1); elist[p1] = (u16)((s4.y - base) << 5);
        int p2 = atomicAdd(&cnt[d4.z - base], 1); elist[p2] = (u16)((s4.z - base) << 5);
        int p3 = atomicAdd(&cnt[d4.w - base], 1); elist[p3] = (u16)((s4.w - base) << 5);
    }
    __syncthreads();
    for (int p = fill_beg; p < fill_end; p++) elist[p] = (u16)(256 << 5);
    __syncthreads();

    // ---- Layer 0 GEMM: B = nf @ W0 (4-node groups, k-unroll 8, MLP=8) ----
    {
        const float* wbase = C + lane * 132;
        for (int gid = w; gid < 64; gid += NW) {
            int n0 = gid * 4;
            const float* nfb = nf + (size_t)(base + n0) * FDIM;
            float acc[4] = {0.f, 0.f, 0.f, 0.f};
#pragma unroll 2
            for (int k0 = 0; k0 < FDIM; k0 += 8) {
                float4 wa = *(const float4*)(wbase + k0);
                float4 wb = *(const float4*)(wbase + k0 + 4);
#pragma unroll
                for (int i = 0; i < 4; i++) {
                    float4 ra = __ldg((const float4*)(nfb + i * FDIM + k0));
                    float4 rb = __ldg((const float4*)(nfb + i * FDIM + k0 + 4));
                    acc[i] = fmaf(ra.x, wa.x, acc[i]);
                    acc[i] = fmaf(ra.y, wa.y, acc[i]);
                    acc[i] = fmaf(ra.z, wa.z, acc[i]);
                    acc[i] = fmaf(ra.w, wa.w, acc[i]);
                    acc[i] = fmaf(rb.x, wb.x, acc[i]);
                    acc[i] = fmaf(rb.y, wb.y, acc[i]);
                    acc[i] = fmaf(rb.z, wb.z, acc[i]);
                    acc[i] = fmaf(rb.w, wb.w, acc[i]);
                }
            }
#pragma unroll
            for (int i = 0; i < 4; i++)
                B[(n0 + i) * 32 + lane] = acc[i];
        }
    }
    __syncthreads();

    // ---- Layer 0 aggregate + tanh -> A (= h1); prefetched indices ----
    for (int n = w; n < 256; n += NW) {
        float acc = B[n * 32 + lane];
        int beg = offs[n], end = offs[n + 1];
        uint2 e2 = *(const uint2*)(elist + beg);
        for (int j = beg; j < end; j += 4) {
            uint2 cur = e2;
            e2 = *(const uint2*)(elist + j + 4);   // over-read safe (<5120)
            acc += agg4(B, cur, lane);
        }
        A[n * 32 + lane] = tanhf((acc + bs[lane]) * invd[n]);
    }
    __syncthreads();

    // ---- stream h1 to global ----
    {
        float4* dst4 = (float4*)(h1g_buf + (size_t)base * 32);
        const float4* src4 = (const float4*)A;
        for (int i = t; i < NPG_ * 32 / 4; i += NT) dst4[i] = src4[i];
    }

    // ---- Layers 1,2 (32->32) ----
    {
        float* hin = A;
        for (int L = 0; L < 2; L++) {
            const float* Wg = (L == 0) ? W1 : W2;
            float bv = bs[32 + L * 32 + lane];
            float* hout = (L == 0) ? C : A;   // L1 -> C (h2), L2 -> A (h3)

            float wr[32];
#pragma unroll
            for (int k = 0; k < 32; k++) wr[k] = __ldg(Wg + k * 32 + lane);
            for (int n = w; n < 256; n += NW) {
                const float* row = hin + n * 32;
                float acc = 0.f;
#pragma unroll
                for (int k = 0; k < 32; k += 4) {
                    float4 r4 = *(const float4*)(row + k);
                    acc = fmaf(r4.x, wr[k],     acc);
                    acc = fmaf(r4.y, wr[k + 1], acc);
                    acc = fmaf(r4.z, wr[k + 2], acc);
                    acc = fmaf(r4.w, wr[k + 3], acc);
                }
                B[n * 32 + lane] = acc;
            }
            __syncthreads();

            for (int n = w; n < 256; n += NW) {
                float acc = B[n * 32 + lane];
                int beg = offs[n], end = offs[n + 1];
                uint2 e2 = *(const uint2*)(elist + beg);
                for (int j = beg; j < end; j += 4) {
                    uint2 cur = e2;
                    e2 = *(const uint2*)(elist + j + 4);
                    acc += agg4(B, cur, lane);
                }
                hout[n * 32 + lane] = tanhf((acc + bv) * invd[n]);
            }
            __syncthreads();
            hin = hout;
        }
    }

    // ---- Layer 3 (32->1) -> z4 ; g1 in B[0..256] ----
    {
        float* g1 = B;
        float w3r = __ldg(W3 + lane);
        float b3v = __ldg(b3);
        if (t == 0) g1[256] = 0.f;
        for (int n = w; n < 256; n += NW) {
            float v = A[n * 32 + lane] * w3r;   // A = h3
#pragma unroll
            for (int off = 16; off; off >>= 1)
                v += __shfl_xor_sync(0xffffffffu, v, off);
            if (lane == 0) g1[n] = v;
        }
        __syncthreads();
        if (t < 256) {
            float acc = g1[t];
            int beg = offs[t], end = offs[t + 1];
            uint2 e2 = *(const uint2*)(elist + beg);
            for (int j = beg; j < end; j += 4) {
                uint2 cur = e2;
                e2 = *(const uint2*)(elist + j + 4);
                acc += (g1[(cur.x & 0xffffu) >> 5] + g1[(cur.x >> 16) >> 5])
                     + (g1[(cur.y & 0xffffu) >> 5] + g1[(cur.y >> 16) >> 5]);
            }
            z4[t] = tanhf((acc + b3v) * invd[t]);
        }
        __syncthreads();
    }

    // ---- sortpool rank selection ----
    int* selrow = cnt;
    if (t < 256) {
        float v = z4[t];
        int r = 0;
#pragma unroll 4
        for (int j0 = 0; j0 < 256; j0 += 4) {
            float4 u4 = *(const float4*)(z4 + j0);
            r += (int)((u4.x > v) || (u4.x == v && (j0    ) < t));
            r += (int)((u4.y > v) || (u4.y == v && (j0 + 1) < t));
            r += (int)((u4.z > v) || (u4.z == v && (j0 + 2) < t));
            r += (int)((u4.w > v) || (u4.w == v && (j0 + 3) < t));
        }
        if (r < KTOP) selrow[r] = t;
    }
    __syncthreads();

    // ---- gather sp[30][97] ----
    float* sp = B + 512;
    for (int i = t; i < KTOP * DLAT; i += NT) {
        int k = i / DLAT, d = i - k * DLAT;
        int n = selrow[k];
        float v;
        if (d < 32)      v = h1g_buf[(size_t)(base + n) * 32 + d];
        else if (d < 64) v = C[n * 32 + d - 32];
        else if (d < 96) v = A[n * 32 + d - 64];
        else             v = z4[n];
        sp[i] = v;
    }
    __syncthreads();

    // ---- conv1 + relu -> out1[16][30] ----
    float* out1 = B + 3600;
    for (int i = t; i < C1_ * KTOP; i += NT) {
        int c = i & 15, k = i >> 4;
        float acc = c1b[c];
        const float* wr = c1w + c * DLAT;
        const float* sr = sp + k * DLAT;
        for (int d = 0; d < DLAT; d++) acc = fmaf(sr[d], wr[d], acc);
        out1[c * KTOP + k] = fmaxf(acc, 0.f);
    }
    __syncthreads();

    // ---- maxpool(2,2) -> pool[16][15] ----
    float* pool = B + 4200;
    if (t < C1_ * 15) {
        int c = t / 15, tt = t - c * 15;
        pool[t] = fmaxf(out1[c * KTOP + 2 * tt], out1[c * KTOP + 2 * tt + 1]);
    }
    __syncthreads();

    // ---- conv2 + relu -> out2[32][11] ----
    float* out2 = B + 4500;
    for (int i = t; i < C2_ * T2_; i += NT) {
        int c2 = i / T2_, tt = i - c2 * T2_;
        float acc = c2b[c2];
#pragma unroll
        for (int c1 = 0; c1 < C1_; c1++) {
            const float* wv = c2w + (c2 * C1_ + c1) * 5;
            const float* pv = pool + c1 * 15 + tt;
#pragma unroll
            for (int j = 0; j < 5; j++) acc = fmaf(pv[j], wv[j], acc);
        }
        out2[i] = fmaxf(acc, 0.f);
    }
    __syncthreads();

    // ---- dense [352]x[352,2] + relu ----
    if (w == 0) {
        float a0 = 0.f, a1 = 0.f;
        for (int i = lane; i < DENSE_; i += 32) {
            float x = out2[i];
            a0 = fmaf(x, ow[i * 2 + 0], a0);
            a1 = fmaf(x, ow[i * 2 + 1], a1);
        }
#pragma unroll
        for (int off = 16; off; off >>= 1) {
            a0 += __shfl_xor_sync(0xffffffffu, a0, off);
            a1 += __shfl_xor_sync(0xffffffffu, a1, off);
        }
        if (lane == 0) {
            out[b * 2 + 0] = fmaxf(a0 + ob[0], 0.f);
            out[b * 2 + 1] = fmaxf(a1 + ob[1], 0.f);
        }
    }
}

extern "C" void kernel_launch(void* const* d_in, const int* in_sizes, int n_in,
                              void* d_out, int out_size)
{
    int iSrc, iDst, iDeg, iW0, ib0, iW1, ib1, iW2, ib2, iW3, ib3;
    int ic1w, ic1b, ic2w, ic2b, iow, iob;
    if (n_in > 1 && in_sizes[1] == NGR * EPG) {
        iSrc = 1; iDst = 2; iDeg = 3;
        iW0 = 4;  ib0 = 5;  iW1 = 6;  ib1 = 7;
        iW2 = 8;  ib2 = 9;  iW3 = 10; ib3 = 11;
        ic1w = 12; ic1b = 13; ic2w = 14; ic2b = 15; iow = 16; iob = 17;
    } else {
        iW0 = 1;  ib0 = 2;  iW1 = 3;  ib1 = 4;
        iW2 = 5;  ib2 = 6;  iW3 = 7;  ib3 = 8;
        ic1w = 9; ic1b = 10; ic2w = 11; ic2b = 12; iow = 13; iob = 14;
        iSrc = 15; iDst = 16; iDeg = 17;
    }

    cudaFuncSetAttribute(dgcnn_kernel,
                         cudaFuncAttributeMaxDynamicSharedMemorySize, SMEM_BYTES);

    dgcnn_kernel<<<NGR, NT, SMEM_BYTES>>>(
        (const float*)d_in[0],
        (const int*)d_in[iSrc], (const int*)d_in[iDst], (const int*)d_in[iDeg],
        (const float*)d_in[iW0], (const float*)d_in[ib0],
        (const float*)d_in[iW1], (const float*)d_in[ib1],
        (const float*)d_in[iW2], (const float*)d_in[ib2],
        (const float*)d_in[iW3], (const float*)d_in[ib3],
        (const float*)d_in[ic1w], (const float*)d_in[ic1b],
        (const float*)d_in[ic2w], (const float*)d_in[ic2b],
        (const float*)d_in[iow], (const float*)d_in[iob],
        (float*)d_out);
}

// round 11
// speedup vs baseline: 1.2981x; 1.0130x over previous
#include <cuda_runtime.h>
#include <math.h>

#define NGR    256
#define NPG_   256
#define FDIM   128
#define EPG    4096
#define DLAT   97
#define KTOP   30
#define C1_    16
#define C2_    32
#define T2_    11
#define DENSE_ 352
#define NT     384
#define NW     12

typedef unsigned int   u32;
typedef unsigned short u16;

// h1 spill buffer (gathered back at sortpool) — static device global
__device__ float h1g_buf[NGR * NPG_ * 32];   // 8MB

// shared layout (float units) — total 28292 floats = 113168 B (2 CTAs/SM)
#define OFF_A     0        // 8192 : h1 -> h3
#define OFF_B     8192     // 8224 : g (257x32, row 256 zeros); later g1 + conv scratch
#define OFF_C     16416    // 8192 : W0 natural [k*32+lane] (4096) during L0 -> h2
#define OFF_Z4    24608    // 256
#define OFF_INVD  24864    // 256
#define OFF_BS    25120    // 96
#define OFF_OFFS  25216    // 257 ints
#define OFF_CNT   25473    // 256 ints
#define OFF_ELIST 25732    // 5120 u16 = 2560 floats
#define SM_FLOATS 28292
static const int SMEM_BYTES = SM_FLOATS * 4;

// aggregate 4 edges with prefetched indices; cur holds indices (pre-shifted by 5)
__device__ __forceinline__ float agg4(const float* __restrict__ Bp, uint2 cur, int lane) {
    int i0 = (int)(cur.x & 0xffffu), i1 = (int)(cur.x >> 16);
    int i2 = (int)(cur.y & 0xffffu), i3 = (int)(cur.y >> 16);
    return (Bp[i0 + lane] + Bp[i1 + lane]) + (Bp[i2 + lane] + Bp[i3 + lane]);
}

__global__ __launch_bounds__(NT, 2)
void dgcnn_kernel(const float* __restrict__ nf,
                  const int* __restrict__ src, const int* __restrict__ dst,
                  const int* __restrict__ degs,
                  const float* __restrict__ W0, const float* __restrict__ b0,
                  const float* __restrict__ W1, const float* __restrict__ b1,
                  const float* __restrict__ W2, const float* __restrict__ b2,
                  const float* __restrict__ W3, const float* __restrict__ b3,
                  const float* __restrict__ c1w, const float* __restrict__ c1b,
                  const float* __restrict__ c2w, const float* __restrict__ c2b,
                  const float* __restrict__ ow, const float* __restrict__ ob,
                  float* __restrict__ out)
{
    extern __shared__ float sm[];
    float* A     = sm + OFF_A;
    float* B     = sm + OFF_B;
    float* C     = sm + OFF_C;
    float* z4    = sm + OFF_Z4;
    float* invd  = sm + OFF_INVD;
    float* bs    = sm + OFF_BS;
    int*   offs  = (int*)(sm + OFF_OFFS);
    int*   cnt   = (int*)(sm + OFF_CNT);
    u16*   elist = (u16*)(sm + OFF_ELIST);

    const int b    = blockIdx.x;
    const int t    = threadIdx.x;
    const int w    = t >> 5;
    const int lane = t & 31;
    const int base = b * NPG_;

    // ---- init ----
    int pdeg = 0;
    if (t < 256) {
        int d = degs[base + t];
        pdeg = (d + 3) & ~3;
        invd[t] = 1.0f / ((float)d + 1.0f);
        cnt[t] = d;
    }
    B[256 * 32 + lane] = 0.f;   // dummy row
    // W0 natural layout: C[k*32 + lane] = W0[k][lane]  (straight copy, conflict-free reads)
    for (int i = t; i < FDIM * 32; i += NT) C[i] = W0[i];
    if (t < 32) { bs[t] = b0[t]; bs[32 + t] = b1[t]; bs[64 + t] = b2[t]; }

    // ---- scan of padded degrees -> offs (exclusive) ----
    if (t < 256) offs[t] = pdeg;
    __syncthreads();
#pragma unroll
    for (int d = 1; d < 256; d <<= 1) {
        int u = (t < 256 && t >= d) ? offs[t - d] : 0;
        __syncthreads();
        if (t < 256) offs[t] += u;
        __syncthreads();
    }
    int fill_beg = 0, fill_end = 0;
    if (t < 256) {
        int inc = offs[t];
        int exc = inc - pdeg;
        __syncthreads();
        offs[t] = exc;
        if (t == 255) offs[256] = inc;
        fill_beg = exc + cnt[t];
    } else {
        __syncthreads();
    }
    __syncthreads();
    if (t < 256) {
        fill_end = offs[t + 1];
        cnt[t] = offs[t];
    }
    __syncthreads();

    // ---- build CSR (values ls<<5 as u16), 4 edges per iteration ----
    for (int i = t * 4; i < EPG; i += NT * 4) {
        int4 s4 = *(const int4*)(src + b * EPG + i);
        int4 d4 = *(const int4*)(dst + b * EPG + i);
        int p0 = atomicAdd(&cnt[d4.x - base], 1); elist[p0] = (u16)((s4.x - base) << 5);
        int p1 = atomicAdd(&cnt[d4.y - base], 1); elist[p1] = (u16)((s4.y - base) << 5);
        int p2 = atomicAdd(&cnt[d4.z - base], 1); elist[p2] = (u16)((s4.z - base) << 5);
        int p3 = atomicAdd(&cnt[d4.w - base], 1); elist[p3] = (u16)((s4.w - base) << 5);
    }
    __syncthreads();
    for (int p = fill_beg; p < fill_end; p++) elist[p] = (u16)(256 << 5);
    __syncthreads();

    // ---- Layer 0 GEMM: B = nf @ W0 ----
    // weights: 4 scalar LDS per k0-step, natural layout (bank = lane, conflict-free)
    // data: broadcast LDG.128 (L2), MLP via unroll
    for (int gid = w; gid < 64; gid += NW) {
        int n0 = gid * 4;
        const float* nfb = nf + (size_t)(base + n0) * FDIM;
        float acc[4] = {0.f, 0.f, 0.f, 0.f};
#pragma unroll 2
        for (int k0 = 0; k0 < FDIM; k0 += 4) {
            float w0v = C[(k0 + 0) * 32 + lane];
            float w1v = C[(k0 + 1) * 32 + lane];
            float w2v = C[(k0 + 2) * 32 + lane];
            float w3v = C[(k0 + 3) * 32 + lane];
#pragma unroll
            for (int i = 0; i < 4; i++) {
                float4 r = __ldg((const float4*)(nfb + i * FDIM + k0));
                acc[i] = fmaf(r.x, w0v, acc[i]);
                acc[i] = fmaf(r.y, w1v, acc[i]);
                acc[i] = fmaf(r.z, w2v, acc[i]);
                acc[i] = fmaf(r.w, w3v, acc[i]);
            }
        }
#pragma unroll
        for (int i = 0; i < 4; i++)
            B[(n0 + i) * 32 + lane] = acc[i];
    }
    __syncthreads();

    // ---- Layer 0 aggregate + tanh -> A (= h1); prefetched indices ----
    for (int n = w; n < 256; n += NW) {
        float acc = B[n * 32 + lane];
        int beg = offs[n], end = offs[n + 1];
        uint2 e2 = *(const uint2*)(elist + beg);
        for (int j = beg; j < end; j += 4) {
            uint2 cur = e2;
            e2 = *(const uint2*)(elist + j + 4);   // over-read safe (<5120)
            acc += agg4(B, cur, lane);
        }
        A[n * 32 + lane] = tanhf((acc + bs[lane]) * invd[n]);
    }
    __syncthreads();

    // ---- stream h1 to global ----
    {
        float4* dst4 = (float4*)(h1g_buf + (size_t)base * 32);
        const float4* src4 = (const float4*)A;
        for (int i = t; i < NPG_ * 32 / 4; i += NT) dst4[i] = src4[i];
    }

    // ---- Layers 1,2 (32->32) ----
    {
        float* hin = A;
        for (int L = 0; L < 2; L++) {
            const float* Wg = (L == 0) ? W1 : W2;
            float bv = bs[32 + L * 32 + lane];
            float* hout = (L == 0) ? C : A;   // L1 -> C (h2), L2 -> A (h3)

            float wr[32];
#pragma unroll
            for (int k = 0; k < 32; k++) wr[k] = __ldg(Wg + k * 32 + lane);
            for (int n = w; n < 256; n += NW) {
                const float* row = hin + n * 32;
                float acc = 0.f;
#pragma unroll
                for (int k = 0; k < 32; k += 4) {
                    float4 r4 = *(const float4*)(row + k);
                    acc = fmaf(r4.x, wr[k],     acc);
                    acc = fmaf(r4.y, wr[k + 1], acc);
                    acc = fmaf(r4.z, wr[k + 2], acc);
                    acc = fmaf(r4.w, wr[k + 3], acc);
                }
                B[n * 32 + lane] = acc;
            }
            __syncthreads();

            for (int n = w; n < 256; n += NW) {
                float acc = B[n * 32 + lane];
                int beg = offs[n], end = offs[n + 1];
                uint2 e2 = *(const uint2*)(elist + beg);
                for (int j = beg; j < end; j += 4) {
                    uint2 cur = e2;
                    e2 = *(const uint2*)(elist + j + 4);
                    acc += agg4(B, cur, lane);
                }
                hout[n * 32 + lane] = tanhf((acc + bv) * invd[n]);
            }
            __syncthreads();
            hin = hout;
        }
    }

    // ---- Layer 3 (32->1) -> z4 ; g1 in B[0..256] ----
    {
        float* g1 = B;
        float w3r = __ldg(W3 + lane);
        float b3v = __ldg(b3);
        if (t == 0) g1[256] = 0.f;
        for (int n = w; n < 256; n += NW) {
            float v = A[n * 32 + lane] * w3r;   // A = h3
#pragma unroll
            for (int off = 16; off; off >>= 1)
                v += __shfl_xor_sync(0xffffffffu, v, off);
            if (lane == 0) g1[n] = v;
        }
        __syncthreads();
        if (t < 256) {
            float acc = g1[t];
            int beg = offs[t], end = offs[t + 1];
            uint2 e2 = *(const uint2*)(elist + beg);
            for (int j = beg; j < end; j += 4) {
                uint2 cur = e2;
                e2 = *(const uint2*)(elist + j + 4);
                acc += (g1[(cur.x & 0xffffu) >> 5] + g1[(cur.x >> 16) >> 5])
                     + (g1[(cur.y & 0xffffu) >> 5] + g1[(cur.y >> 16) >> 5]);
            }
            z4[t] = tanhf((acc + b3v) * invd[t]);
        }
        __syncthreads();
    }

    // ---- sortpool rank selection ----
    int* selrow = cnt;
    if (t < 256) {
        float v = z4[t];
        int r = 0;
#pragma unroll 4
        for (int j0 = 0; j0 < 256; j0 += 4) {
            float4 u4 = *(const float4*)(z4 + j0);
            r += (int)((u4.x > v) || (u4.x == v && (j0    ) < t));
            r += (int)((u4.y > v) || (u4.y == v && (j0 + 1) < t));
            r += (int)((u4.z > v) || (u4.z == v && (j0 + 2) < t));
            r += (int)((u4.w > v) || (u4.w == v && (j0 + 3) < t));
        }
        if (r < KTOP) selrow[r] = t;
    }
    __syncthreads();

    // ---- gather sp[30][97] ----
    float* sp = B + 512;
    for (int i = t; i < KTOP * DLAT; i += NT) {
        int k = i / DLAT, d = i - k * DLAT;
        int n = selrow[k];
        float v;
        if (d < 32)      v = h1g_buf[(size_t)(base + n) * 32 + d];
        else if (d < 64) v = C[n * 32 + d - 32];
        else if (d < 96) v = A[n * 32 + d - 64];
        else             v = z4[n];
        sp[i] = v;
    }
    __syncthreads();

    // ---- conv1 + relu -> out1[16][30] ----
    float* out1 = B + 3600;
    for (int i = t; i < C1_ * KTOP; i += NT) {
        int c = i & 15, k = i >> 4;
        float acc = c1b[c];
        const float* wr = c1w + c * DLAT;
        const float* sr = sp + k * DLAT;
        for (int d = 0; d < DLAT; d++) acc = fmaf(sr[d], wr[d], acc);
        out1[c * KTOP + k] = fmaxf(acc, 0.f);
    }
    __syncthreads();

    // ---- maxpool(2,2) -> pool[16][15] ----
    float* pool = B + 4200;
    if (t < C1_ * 15) {
        int c = t / 15, tt = t - c * 15;
        pool[t] = fmaxf(out1[c * KTOP + 2 * tt], out1[c * KTOP + 2 * tt + 1]);
    }
    __syncthreads();

    // ---- conv2 + relu -> out2[32][11] ----
    float* out2 = B + 4500;
    for (int i = t; i < C2_ * T2_; i += NT) {
        int c2 = i / T2_, tt = i - c2 * T2_;
        float acc = c2b[c2];
#pragma unroll
        for (int c1 = 0; c1 < C1_; c1++) {
            const float* wv = c2w + (c2 * C1_ + c1) * 5;
            const float* pv = pool + c1 * 15 + tt;
#pragma unroll
            for (int j = 0; j < 5; j++) acc = fmaf(pv[j], wv[j], acc);
        }
        out2[i] = fmaxf(acc, 0.f);
    }
    __syncthreads();

    // ---- dense [352]x[352,2] + relu ----
    if (w == 0) {
        float a0 = 0.f, a1 = 0.f;
        for (int i = lane; i < DENSE_; i += 32) {
            float x = out2[i];
            a0 = fmaf(x, ow[i * 2 + 0], a0);
            a1 = fmaf(x, ow[i * 2 + 1], a1);
        }
#pragma unroll
        for (int off = 16; off; off >>= 1) {
            a0 += __shfl_xor_sync(0xffffffffu, a0, off);
            a1 += __shfl_xor_sync(0xffffffffu, a1, off);
        }
        if (lane == 0) {
            out[b * 2 + 0] = fmaxf(a0 + ob[0], 0.f);
            out[b * 2 + 1] = fmaxf(a1 + ob[1], 0.f);
        }
    }
}

extern "C" void kernel_launch(void* const* d_in, const int* in_sizes, int n_in,
                              void* d_out, int out_size)
{
    int iSrc, iDst, iDeg, iW0, ib0, iW1, ib1, iW2, ib2, iW3, ib3;
    int ic1w, ic1b, ic2w, ic2b, iow, iob;
    if (n_in > 1 && in_sizes[1] == NGR * EPG) {
        iSrc = 1; iDst = 2; iDeg = 3;
        iW0 = 4;  ib0 = 5;  iW1 = 6;  ib1 = 7;
        iW2 = 8;  ib2 = 9;  iW3 = 10; ib3 = 11;
        ic1w = 12; ic1b = 13; ic2w = 14; ic2b = 15; iow = 16; iob = 17;
    } else {
        iW0 = 1;  ib0 = 2;  iW1 = 3;  ib1 = 4;
        iW2 = 5;  ib2 = 6;  iW3 = 7;  ib3 = 8;
        ic1w = 9; ic1b = 10; ic2w = 11; ic2b = 12; iow = 13; iob = 14;
        iSrc = 15; iDst = 16; iDeg = 17;
    }

    cudaFuncSetAttribute(dgcnn_kernel,
                         cudaFuncAttributeMaxDynamicSharedMemorySize, SMEM_BYTES);

    dgcnn_kernel<<<NGR, NT, SMEM_BYTES>>>(
        (const float*)d_in[0],
        (const int*)d_in[iSrc], (const int*)d_in[iDst], (const int*)d_in[iDeg],
        (const float*)d_in[iW0], (const float*)d_in[ib0],
        (const float*)d_in[iW1], (const float*)d_in[ib1],
        (const float*)d_in[iW2], (const float*)d_in[ib2],
        (const float*)d_in[iW3], (const float*)d_in[ib3],
        (const float*)d_in[ic1w], (const float*)d_in[ic1b],
        (const float*)d_in[ic2w], (const float*)d_in[ic2b],
        (const float*)d_in[iow], (const float*)d_in[iob],
        (float*)d_out);
}